// round 16
// baseline (speedup 1.0000x reference)
#include <cuda_runtime.h>
#include <cuda_bf16.h>

// CenterNet GT heatmap rendering — single kernel, band-gather, NO atomics.
//
// hm:      [N, C, H, W] f32 (shape-only)      -> d_in[0]
// bboxes:  [N, NOBJ, 5] f32 (x1,y1,x2,y2,val) -> d_in[1]
// out:     [N, C, H, W] f32, C == 1
//
// One graph node, grid (8 bands x 16 batches) = 128 blocks, 512 threads.
// Block owns a 16-row band of one batch plane; warp w owns row y0 + w.
// Each lane accumulates 4 pixels (x = lane + {0,32,64,96}) in registers.
//   Phase 1: threads 0..127 compute the 128 objects' gaussian params and
//            compact the band-intersecting ones into smem (~25 of 128).
//   Phase 2: per warp, per object: warp-uniform row cull (|dy|>r), then
//            warp-uniform x-chunk cull (usually 1 of 4 chunks live), then
//            g = __expf((dx^2+dy^2)*c), m = fmax(m, inside ? g : 0).
//   Phase 3: 4 coalesced STG.32 per warp — every pixel written, so no
//            zero-init and no ordering problem (poison overwritten).
// No global atomics anywhere; the only smem atomic is the list compaction.

#define HN 16
#define HC 1
#define HH 128
#define HW 128
#define NOBJ 128
#define BAND_H 16
#define BANDS (HH / BAND_H)            // 8
#define NTHREADS 512                   // 16 warps = 16 rows
#define MIN_OVERLAP 0.7f

__device__ __forceinline__ float gaussian_radius_f(float w, float h) {
    // mirrors the reference fp32 math op-for-op
    const float mo = MIN_OVERLAP;
    float b1 = h + w;
    float c1 = w * h * ((1.0f - mo) / (1.0f + mo));
    float sq1 = sqrtf(b1 * b1 - 4.0f * 1.0f * c1);
    float r1 = (b1 + sq1) * 0.5f;

    float b2 = 2.0f * (h + w);
    float c2 = (1.0f - mo) * w * h;
    float sq2 = sqrtf(b2 * b2 - 4.0f * 4.0f * c2);
    float r2 = (b2 + sq2) * 0.5f;

    float a3 = 4.0f * mo;
    float b3 = -2.0f * mo * (h + w);
    float c3 = (mo - 1.0f) * w * h;
    float sq3 = sqrtf(b3 * b3 - 4.0f * a3 * c3);
    float r3 = (b3 + sq3) * 0.5f;

    return fminf(fminf(r1, r2), r3);
}

__global__ void __launch_bounds__(NTHREADS)
cn_band_kernel(const float* __restrict__ bboxes,
               float* __restrict__ out) {
    __shared__ float4 s_q[NOBJ];       // compacted: {cx, cy, r, -1/(2s^2)}
    __shared__ int    s_cnt;

    const int tid   = threadIdx.x;
    const int wid   = tid >> 5;
    const int lane  = tid & 31;
    const int band  = blockIdx.x;      // 0..7
    const int batch = blockIdx.y;      // 0..15
    const int y0    = band * BAND_H;

    // ---- Phase 1: params + band cull (threads 0..127) ----
    // issue the loads first; scoreboard covers the latency
    float x1, y1, x2, y2, valf;
    if (tid < NOBJ) {
        const float* p = bboxes + (batch * NOBJ + tid) * 5;
        x1 = p[0] * (float)HW;
        y1 = p[1] * (float)HH;
        x2 = p[2] * (float)HW;
        y2 = p[3] * (float)HH;
        valf = p[4];
    }
    if (tid == 0) s_cnt = 0;
    __syncthreads();

    if (tid < NOBJ) {
        float bw = x2 - x1;
        float bh = y2 - y1;
        if (valf == 1.0f && bw > 0.0f && bh > 0.0f) {
            float r = gaussian_radius_f(bw, bh);
            if (!(r == r)) r = 0.0f;        // jnp.nan_to_num
            r = fmaxf(r, 0.0f);

            int ri  = (int)r;               // trunc toward zero, r >= 0
            int cxi = (int)((x1 + x2) * 0.5f);
            int cyi = (int)((y1 + y2) * 0.5f);

            // band-row intersection: [cy-r, cy+r] vs [y0, y0+15]
            if (cyi + ri >= y0 && cyi - ri <= y0 + BAND_H - 1) {
                float sigma = (float)(2 * ri + 1) / 6.0f;
                float c = -1.0f / (2.0f * sigma * sigma);
                int slot = atomicAdd(&s_cnt, 1);
                // ints <= 128 exact in fp32
                s_q[slot] = make_float4((float)cxi, (float)cyi, (float)ri, c);
            }
        }
    }
    __syncthreads();

    // ---- Phase 2: warp = row y0 + wid; 4 register accumulators ----
    const float yyf   = (float)(y0 + wid);
    const float lanef = (float)lane;
    const int cnt = s_cnt;

    float m0 = 0.f, m1 = 0.f, m2 = 0.f, m3 = 0.f;

    for (int j = 0; j < cnt; j++) {
        float4 q = s_q[j];                  // broadcast LDS.128
        float dy = yyf - q.y;
        if (fabsf(dy) > q.z) continue;      // warp-uniform row cull
        float t = dy * dy;

        // chunk k live iff [cx-r, cx+r] overlaps [32k, 32k+31] (warp-uniform)
        if (q.x + q.z >= 0.f && q.x - q.z <= 31.f) {
            float dx = lanef - q.x;
            float g = __expf(fmaf(dx, dx, t) * q.w);
            m0 = fmaxf(m0, fabsf(dx) <= q.z ? g : 0.f);
        }
        if (q.x + q.z >= 32.f && q.x - q.z <= 63.f) {
            float dx = (lanef + 32.f) - q.x;
            float g = __expf(fmaf(dx, dx, t) * q.w);
            m1 = fmaxf(m1, fabsf(dx) <= q.z ? g : 0.f);
        }
        if (q.x + q.z >= 64.f && q.x - q.z <= 95.f) {
            float dx = (lanef + 64.f) - q.x;
            float g = __expf(fmaf(dx, dx, t) * q.w);
            m2 = fmaxf(m2, fabsf(dx) <= q.z ? g : 0.f);
        }
        if (q.x + q.z >= 96.f && q.x - q.z <= 127.f) {
            float dx = (lanef + 96.f) - q.x;
            float g = __expf(fmaf(dx, dx, t) * q.w);
            m3 = fmaxf(m3, fabsf(dx) <= q.z ? g : 0.f);
        }
    }

    // ---- Phase 3: coalesced stores; every pixel written ----
    float* row = out + batch * (HH * HW) + (y0 + wid) * HW + lane;
    row[0]  = m0;
    row[32] = m1;
    row[64] = m2;
    row[96] = m3;
}

extern "C" void kernel_launch(void* const* d_in, const int* in_sizes, int n_in,
                              void* d_out, int out_size) {
    const float* bboxes = (const float*)d_in[1];
    float* out = (float*)d_out;

    dim3 grid(BANDS, HN);   // (8, 16) = 128 blocks
    cn_band_kernel<<<grid, NTHREADS>>>(bboxes, out);
}